// round 3
// baseline (speedup 1.0000x reference)
#include <cuda_runtime.h>

#define N_NODES   100000
#define N_EDGES   1600000
#define N_GRAPHS  5000
#define ND        16
#define ED        16
#define HID       20
#define H2        10
#define HP        (HID/2)   // 10 f32x2 pairs
#define H2P       (H2/2)    // 5 pairs
#define XSTRIDE   12        // g_x row stride (10 used + 2 pad, 48B rows)

// Scratch
__device__ float g_x [N_NODES * XSTRIDE];  // scatter-sum of msg@W1 per node (10-wide)
__device__ float g_pa[N_NODES * HID];
__device__ float g_pb[N_NODES * HID];
__device__ float g_g [N_GRAPHS * H2];

// ---- packed f32x2 helpers -------------------------------------------------
__device__ __forceinline__ unsigned long long fma2(unsigned long long a,
                                                   unsigned long long b,
                                                   unsigned long long c) {
    unsigned long long d;
    asm("fma.rn.f32x2 %0, %1, %2, %3;" : "=l"(d) : "l"(a), "l"(b), "l"(c));
    return d;
}
__device__ __forceinline__ unsigned long long bcast2(float x) {
    unsigned long long d;
    asm("mov.b64 %0, {%1, %1};" : "=l"(d) : "f"(x));
    return d;
}
__device__ __forceinline__ float2 unpack2(unsigned long long v) {
    float2 r;
    asm("mov.b64 {%0, %1}, %2;" : "=f"(r.x), "=f"(r.y) : "l"(v));
    return r;
}

// ---------------------------------------------------------------------------
// Kernel 1: per-node projections pa = A@Wa, pb = A@Wb  (+ fused zeroing)
// ---------------------------------------------------------------------------
__global__ void node_proj_kernel(const float* __restrict__ node_attr,
                                 const float* __restrict__ W_msg) {
    __shared__ __align__(8) float sWa[ND * HID];
    __shared__ __align__(8) float sWb[ND * HID];
    for (int i = threadIdx.x; i < ND * HID; i += blockDim.x) {
        sWa[i] = W_msg[i];
        sWb[i] = W_msg[ND * HID + i];
    }
    __syncthreads();
    const unsigned long long* wa2 = (const unsigned long long*)sWa;
    const unsigned long long* wb2 = (const unsigned long long*)sWb;

    int n = blockIdx.x * blockDim.x + threadIdx.x;

    // fused zero of g_g (50000 floats)
    if (n < (N_GRAPHS * H2) / 4)
        ((float4*)g_g)[n] = make_float4(0.f, 0.f, 0.f, 0.f);

    if (n >= N_NODES) return;

    // fused zero of this node's g_x row (12 floats, 48B)
    {
        const float4 z = make_float4(0.f, 0.f, 0.f, 0.f);
        float4* xr = (float4*)(g_x + (size_t)n * XSTRIDE);
#pragma unroll
        for (int q = 0; q < 3; q++) xr[q] = z;
    }

    float a[ND];
    const float4* ap = (const float4*)(node_attr + (size_t)n * ND);
#pragma unroll
    for (int q = 0; q < 4; q++) {
        float4 v = ap[q];
        a[4*q+0] = v.x; a[4*q+1] = v.y; a[4*q+2] = v.z; a[4*q+3] = v.w;
    }

    unsigned long long acc[HP];
#pragma unroll
    for (int p = 0; p < HP; p++) acc[p] = 0ull;
#pragma unroll
    for (int k = 0; k < ND; k++) {
        unsigned long long ak = bcast2(a[k]);
#pragma unroll
        for (int p = 0; p < HP; p++) acc[p] = fma2(ak, wa2[k * HP + p], acc[p]);
    }
    {
        float2* pa = (float2*)(g_pa + (size_t)n * HID);
#pragma unroll
        for (int p = 0; p < HP; p++) pa[p] = unpack2(acc[p]);
    }

#pragma unroll
    for (int p = 0; p < HP; p++) acc[p] = 0ull;
#pragma unroll
    for (int k = 0; k < ND; k++) {
        unsigned long long ak = bcast2(a[k]);
#pragma unroll
        for (int p = 0; p < HP; p++) acc[p] = fma2(ak, wb2[k * HP + p], acc[p]);
    }
    {
        float2* pb = (float2*)(g_pb + (size_t)n * HID);
#pragma unroll
        for (int p = 0; p < HP; p++) pb[p] = unpack2(acc[p]);
    }
}

// ---------------------------------------------------------------------------
// Kernel 2: edge message, fold W1, scatter 10-wide partial:
//   msg = relu(pa[src] + pb[dst] + edge_attr[e]@We + b_msg)   [20]
//   y   = msg @ W1                                            [10]
//   g_x[dst] += y   (v4 + v4 + v2 REDG)
// ---------------------------------------------------------------------------
__global__ __launch_bounds__(256) void edge_kernel(
        const int*   __restrict__ edge_index,
        const float* __restrict__ edge_attr,
        const float* __restrict__ W_msg,
        const float* __restrict__ b_msg,
        const float* __restrict__ W1) {
    __shared__ __align__(8) float sWe[ED * HID];
    __shared__ __align__(8) float sb[HID];
    __shared__ __align__(8) float sW1[HID * H2];
    for (int i = threadIdx.x; i < ED * HID; i += blockDim.x)
        sWe[i] = W_msg[2 * ND * HID + i];
    for (int i = threadIdx.x; i < HID; i += blockDim.x)
        sb[i] = b_msg[i];
    for (int i = threadIdx.x; i < HID * H2; i += blockDim.x)
        sW1[i] = W1[i];
    __syncthreads();
    const unsigned long long* we2 = (const unsigned long long*)sWe;
    const unsigned long long* sb2 = (const unsigned long long*)sb;
    const unsigned long long* w12 = (const unsigned long long*)sW1;

    int e = blockIdx.x * blockDim.x + threadIdx.x;
    if (e >= N_EDGES) return;

    int src = __ldg(edge_index + e);
    int dst = __ldg(edge_index + N_EDGES + e);

    // issue gathers early (independent of matmul)
    const float4* pap = (const float4*)(g_pa + (size_t)src * HID);
    const float4* pbp = (const float4*)(g_pb + (size_t)dst * HID);
    float4 va[5], vb[5];
#pragma unroll
    for (int q = 0; q < 5; q++) { va[q] = pap[q]; vb[q] = pbp[q]; }

    unsigned long long acc[HP];
#pragma unroll
    for (int p = 0; p < HP; p++) acc[p] = sb2[p];

    const float4* ep = (const float4*)(edge_attr + (size_t)e * ED);
#pragma unroll
    for (int q = 0; q < 4; q++) {
        float4 v = ep[q];
        float ek[4] = {v.x, v.y, v.z, v.w};
#pragma unroll
        for (int t = 0; t < 4; t++) {
            unsigned long long b = bcast2(ek[t]);
#pragma unroll
            for (int p = 0; p < HP; p++)
                acc[p] = fma2(b, we2[(4*q + t) * HP + p], acc[p]);
        }
    }

    float m[HID];
#pragma unroll
    for (int p = 0; p < HP; p++) {
        float2 t = unpack2(acc[p]);
        m[2*p] = t.x; m[2*p+1] = t.y;
    }
#pragma unroll
    for (int q = 0; q < 5; q++) {
        m[4*q+0] += va[q].x + vb[q].x;
        m[4*q+1] += va[q].y + vb[q].y;
        m[4*q+2] += va[q].z + vb[q].z;
        m[4*q+3] += va[q].w + vb[q].w;
    }
#pragma unroll
    for (int j = 0; j < HID; j++) m[j] = fmaxf(m[j], 0.f);

    // y = m @ W1   (20x10), packed
    unsigned long long yacc[H2P];
#pragma unroll
    for (int p = 0; p < H2P; p++) yacc[p] = 0ull;
#pragma unroll
    for (int k = 0; k < HID; k++) {
        unsigned long long mk = bcast2(m[k]);
#pragma unroll
        for (int p = 0; p < H2P; p++)
            yacc[p] = fma2(mk, w12[k * H2P + p], yacc[p]);
    }
    float y[H2];
#pragma unroll
    for (int p = 0; p < H2P; p++) {
        float2 t = unpack2(yacc[p]);
        y[2*p] = t.x; y[2*p+1] = t.y;
    }

    float* xr = g_x + (size_t)dst * XSTRIDE;   // 48B rows, 16B-aligned
    asm volatile("red.global.add.v4.f32 [%0], {%1,%2,%3,%4};"
                 :: "l"(xr), "f"(y[0]), "f"(y[1]), "f"(y[2]), "f"(y[3]) : "memory");
    asm volatile("red.global.add.v4.f32 [%0], {%1,%2,%3,%4};"
                 :: "l"(xr + 4), "f"(y[4]), "f"(y[5]), "f"(y[6]), "f"(y[7]) : "memory");
    asm volatile("red.global.add.v2.f32 [%0], {%1,%2};"
                 :: "l"(xr + 8), "f"(y[8]), "f"(y[9]) : "memory");
}

// ---------------------------------------------------------------------------
// Kernel 3: node stage is now just relu(x + b1) + pooling scatter
// ---------------------------------------------------------------------------
__global__ __launch_bounds__(128) void node_mlp_kernel(
        const int*   __restrict__ batch,
        const float* __restrict__ b1) {
    __shared__ float sb[H2];
    if (threadIdx.x < H2) sb[threadIdx.x] = b1[threadIdx.x];
    __syncthreads();

    int n = blockIdx.x * blockDim.x + threadIdx.x;
    if (n >= N_NODES) return;

    int b = __ldg(batch + n);     // issue first

    const float4* xp = (const float4*)(g_x + (size_t)n * XSTRIDE);
    float4 v0 = xp[0];
    float4 v1 = xp[1];
    float2 v2 = *(const float2*)(g_x + (size_t)n * XSTRIDE + 8);

    float y[H2];
    y[0]=v0.x; y[1]=v0.y; y[2]=v0.z; y[3]=v0.w;
    y[4]=v1.x; y[5]=v1.y; y[6]=v1.z; y[7]=v1.w;
    y[8]=v2.x; y[9]=v2.y;
#pragma unroll
    for (int j = 0; j < H2; j++) y[j] = fmaxf(y[j] + sb[j], 0.f);

    float* gr = g_g + (size_t)b * H2;
#pragma unroll
    for (int q = 0; q < 5; q++) {
        asm volatile("red.global.add.v2.f32 [%0], {%1,%2};"
                     :: "l"(gr + 2*q), "f"(y[2*q]), "f"(y[2*q+1])
                     : "memory");
    }
}

// ---------------------------------------------------------------------------
// Kernel 4: graph MLP
// ---------------------------------------------------------------------------
__global__ __launch_bounds__(64) void graph_mlp_kernel(
        const float* __restrict__ W2,
        const float* __restrict__ b2,
        const float* __restrict__ W3,
        const float* __restrict__ b3,
        float* __restrict__ out) {
    __shared__ float sW2[H2 * H2];
    __shared__ float sb2[H2];
    __shared__ float sW3[H2];
    __shared__ float sb3;
    for (int i = threadIdx.x; i < H2 * H2; i += blockDim.x) sW2[i] = W2[i];
    if (threadIdx.x < H2) { sb2[threadIdx.x] = b2[threadIdx.x]; sW3[threadIdx.x] = W3[threadIdx.x]; }
    if (threadIdx.x == 0) sb3 = b3[0];
    __syncthreads();

    int g = blockIdx.x * blockDim.x + threadIdx.x;
    if (g >= N_GRAPHS) return;

    float v[H2];
    const float2* gp = (const float2*)(g_g + (size_t)g * H2);
#pragma unroll
    for (int q = 0; q < 5; q++) {
        float2 t = gp[q];
        v[2*q] = t.x; v[2*q+1] = t.y;
    }

    float o = sb3;
#pragma unroll
    for (int j = 0; j < H2; j++) {
        float h = sb2[j];
#pragma unroll
        for (int k = 0; k < H2; k++) h = fmaf(v[k], sW2[k * H2 + j], h);
        o = fmaf(fmaxf(h, 0.f), sW3[j], o);
    }
    out[g] = o;
}

// ---------------------------------------------------------------------------
extern "C" void kernel_launch(void* const* d_in, const int* in_sizes, int n_in,
                              void* d_out, int out_size) {
    const int*   edge_index = (const int*)  d_in[0];
    const float* node_attr  = (const float*)d_in[1];
    const float* edge_attr  = (const float*)d_in[2];
    const int*   batch      = (const int*)  d_in[3];
    const float* W_msg      = (const float*)d_in[4];
    const float* b_msg      = (const float*)d_in[5];
    const float* W1         = (const float*)d_in[6];
    const float* b1         = (const float*)d_in[7];
    const float* W2         = (const float*)d_in[8];
    const float* b2         = (const float*)d_in[9];
    const float* W3         = (const float*)d_in[10];
    const float* b3         = (const float*)d_in[11];
    float* out = (float*)d_out;

    node_proj_kernel<<<(N_NODES + 255) / 256, 256>>>(node_attr, W_msg);
    edge_kernel<<<(N_EDGES + 255) / 256, 256>>>(edge_index, edge_attr, W_msg, b_msg, W1);
    node_mlp_kernel<<<(N_NODES + 127) / 128, 128>>>(batch, b1);
    graph_mlp_kernel<<<(N_GRAPHS + 63) / 64, 64>>>(W2, b2, W3, b3, out);
}

// round 4
// speedup vs baseline: 1.0176x; 1.0176x over previous
#include <cuda_runtime.h>

#define N_NODES   100000
#define N_EDGES   1600000
#define N_GRAPHS  5000
#define ND        16
#define ED        16
#define HID       20
#define H2        10
#define HP        (HID/2)
#define H2P       (H2/2)
#define PSTRIDE   32        // padded row stride (128B lines) for g_pa/g_pb/g_x

__device__ __align__(128) float g_x [N_NODES * PSTRIDE];
__device__ __align__(128) float g_pa[N_NODES * PSTRIDE];
__device__ __align__(128) float g_pb[N_NODES * PSTRIDE];
__device__ __align__(128) float g_g [N_GRAPHS * H2];

// ---- packed f32x2 helpers -------------------------------------------------
__device__ __forceinline__ unsigned long long fma2(unsigned long long a,
                                                   unsigned long long b,
                                                   unsigned long long c) {
    unsigned long long d;
    asm("fma.rn.f32x2 %0, %1, %2, %3;" : "=l"(d) : "l"(a), "l"(b), "l"(c));
    return d;
}
__device__ __forceinline__ unsigned long long bcast2(float x) {
    unsigned long long d;
    asm("mov.b64 %0, {%1, %1};" : "=l"(d) : "f"(x));
    return d;
}
__device__ __forceinline__ float2 unpack2(unsigned long long v) {
    float2 r;
    asm("mov.b64 {%0, %1}, %2;" : "=f"(r.x), "=f"(r.y) : "l"(v));
    return r;
}

// ---------------------------------------------------------------------------
// Kernel 1: per-node projections into 128B-padded rows (+ fused zeroing)
// ---------------------------------------------------------------------------
__global__ void node_proj_kernel(const float* __restrict__ node_attr,
                                 const float* __restrict__ W_msg) {
    __shared__ __align__(8) float sWa[ND * HID];
    __shared__ __align__(8) float sWb[ND * HID];
    for (int i = threadIdx.x; i < ND * HID; i += blockDim.x) {
        sWa[i] = W_msg[i];
        sWb[i] = W_msg[ND * HID + i];
    }
    __syncthreads();
    const unsigned long long* wa2 = (const unsigned long long*)sWa;
    const unsigned long long* wb2 = (const unsigned long long*)sWb;

    int n = blockIdx.x * blockDim.x + threadIdx.x;

    if (n < (N_GRAPHS * H2) / 4)
        ((float4*)g_g)[n] = make_float4(0.f, 0.f, 0.f, 0.f);

    if (n >= N_NODES) return;

    // zero the 20 used floats of this node's g_x row
    {
        const float4 z = make_float4(0.f, 0.f, 0.f, 0.f);
        float4* xr = (float4*)(g_x + (size_t)n * PSTRIDE);
#pragma unroll
        for (int q = 0; q < 5; q++) xr[q] = z;
    }

    float a[ND];
    const float4* ap = (const float4*)(node_attr + (size_t)n * ND);
#pragma unroll
    for (int q = 0; q < 4; q++) {
        float4 v = ap[q];
        a[4*q+0] = v.x; a[4*q+1] = v.y; a[4*q+2] = v.z; a[4*q+3] = v.w;
    }

    unsigned long long acc[HP];
#pragma unroll
    for (int p = 0; p < HP; p++) acc[p] = 0ull;
#pragma unroll
    for (int k = 0; k < ND; k++) {
        unsigned long long ak = bcast2(a[k]);
#pragma unroll
        for (int p = 0; p < HP; p++) acc[p] = fma2(ak, wa2[k * HP + p], acc[p]);
    }
    {
        float2* pa = (float2*)(g_pa + (size_t)n * PSTRIDE);
#pragma unroll
        for (int p = 0; p < HP; p++) pa[p] = unpack2(acc[p]);
    }

#pragma unroll
    for (int p = 0; p < HP; p++) acc[p] = 0ull;
#pragma unroll
    for (int k = 0; k < ND; k++) {
        unsigned long long ak = bcast2(a[k]);
#pragma unroll
        for (int p = 0; p < HP; p++) acc[p] = fma2(ak, wb2[k * HP + p], acc[p]);
    }
    {
        float2* pb = (float2*)(g_pb + (size_t)n * PSTRIDE);
#pragma unroll
        for (int p = 0; p < HP; p++) pb[p] = unpack2(acc[p]);
    }
}

// ---------------------------------------------------------------------------
// Kernel 2: edge message + scatter, 4 threads per edge.
// Thread q of an edge owns dims {4q..4q+3} and {16+q}.
// Gathers become quad-cooperative: one LDG.128 per thread hits the SAME
// 128B line as its 3 quad partners -> 8 lines/warp-instr instead of 32.
// ---------------------------------------------------------------------------
__global__ __launch_bounds__(256) void edge_kernel(
        const int*   __restrict__ edge_index,
        const float* __restrict__ edge_attr,
        const float* __restrict__ W_msg,
        const float* __restrict__ b_msg) {
    __shared__ __align__(16) float sWe[ED * HID];
    __shared__ __align__(16) float sb[HID];
    for (int i = threadIdx.x; i < ED * HID; i += blockDim.x)
        sWe[i] = W_msg[2 * ND * HID + i];
    for (int i = threadIdx.x; i < HID; i += blockDim.x)
        sb[i] = b_msg[i];
    __syncthreads();
    const unsigned long long* we2 = (const unsigned long long*)sWe;

    int t = blockIdx.x * blockDim.x + threadIdx.x;
    int e = t >> 2;
    int q = t & 3;
    if (e >= N_EDGES) return;

    int src = __ldg(edge_index + e);
    int dst = __ldg(edge_index + N_EDGES + e);

    // quad-cooperative gathers (each quad covers one 128B row line)
    const float* par = g_pa + (size_t)src * PSTRIDE;
    const float* pbr = g_pb + (size_t)dst * PSTRIDE;
    float4 a4 = *(const float4*)(par + 4 * q);
    float  a1 = par[16 + q];
    float4 b4 = *(const float4*)(pbr + 4 * q);
    float  b1 = pbr[16 + q];

    // full edge_attr row (quad lanes read same addresses -> broadcast)
    const float4* ep = (const float4*)(edge_attr + (size_t)e * ED);
    float ea[ED];
#pragma unroll
    for (int c = 0; c < 4; c++) {
        float4 v = ep[c];
        ea[4*c+0] = v.x; ea[4*c+1] = v.y; ea[4*c+2] = v.z; ea[4*c+3] = v.w;
    }

    // c = b + ea @ We for this thread's 5 dims (2 packed pairs + 1 scalar)
    unsigned long long acc0 = *(const unsigned long long*)(sb + 4 * q);
    unsigned long long acc1 = *(const unsigned long long*)(sb + 4 * q + 2);
    float accs = sb[16 + q];
#pragma unroll
    for (int k = 0; k < ED; k++) {
        unsigned long long ek = bcast2(ea[k]);
        acc0 = fma2(ek, we2[k * HP + 2 * q + 0], acc0);
        acc1 = fma2(ek, we2[k * HP + 2 * q + 1], acc1);
        accs = fmaf(ea[k], sWe[k * HID + 16 + q], accs);
    }

    float2 c0 = unpack2(acc0);
    float2 c1 = unpack2(acc1);
    float m0 = fmaxf(c0.x + a4.x + b4.x, 0.f);
    float m1 = fmaxf(c0.y + a4.y + b4.y, 0.f);
    float m2 = fmaxf(c1.x + a4.z + b4.z, 0.f);
    float m3 = fmaxf(c1.y + a4.w + b4.w, 0.f);
    float m4 = fmaxf(accs + a1 + b1, 0.f);

    float* xr = g_x + (size_t)dst * PSTRIDE;
    asm volatile("red.global.add.v4.f32 [%0], {%1,%2,%3,%4};"
                 :: "l"(xr + 4 * q), "f"(m0), "f"(m1), "f"(m2), "f"(m3) : "memory");
    asm volatile("red.global.add.f32 [%0], %1;"
                 :: "l"(xr + 16 + q), "f"(m4) : "memory");
}

// ---------------------------------------------------------------------------
// Kernel 3: node MLP relu(x@W1+b1) + graph pooling
// ---------------------------------------------------------------------------
__global__ __launch_bounds__(128) void node_mlp_kernel(
        const int*   __restrict__ batch,
        const float* __restrict__ W1,
        const float* __restrict__ b1) {
    __shared__ __align__(8) float sW[HID * H2];
    __shared__ __align__(8) float sb[H2];
    for (int i = threadIdx.x; i < HID * H2; i += blockDim.x) sW[i] = W1[i];
    for (int i = threadIdx.x; i < H2; i += blockDim.x) sb[i] = b1[i];
    __syncthreads();
    const unsigned long long* w2 = (const unsigned long long*)sW;
    const unsigned long long* sb2 = (const unsigned long long*)sb;

    int n = blockIdx.x * blockDim.x + threadIdx.x;
    if (n >= N_NODES) return;

    int b = __ldg(batch + n);

    float x[HID];
    const float4* xp = (const float4*)(g_x + (size_t)n * PSTRIDE);
#pragma unroll
    for (int qq = 0; qq < 5; qq++) {
        float4 v = xp[qq];
        x[4*qq+0] = v.x; x[4*qq+1] = v.y; x[4*qq+2] = v.z; x[4*qq+3] = v.w;
    }

    unsigned long long acc[H2P];
#pragma unroll
    for (int p = 0; p < H2P; p++) acc[p] = sb2[p];
#pragma unroll
    for (int k = 0; k < HID; k++) {
        unsigned long long xk = bcast2(x[k]);
#pragma unroll
        for (int p = 0; p < H2P; p++) acc[p] = fma2(xk, w2[k * H2P + p], acc[p]);
    }

    float y[H2];
#pragma unroll
    for (int p = 0; p < H2P; p++) {
        float2 tt = unpack2(acc[p]);
        y[2*p]   = fmaxf(tt.x, 0.f);
        y[2*p+1] = fmaxf(tt.y, 0.f);
    }

    float* gr = g_g + (size_t)b * H2;
#pragma unroll
    for (int qq = 0; qq < 5; qq++) {
        asm volatile("red.global.add.v2.f32 [%0], {%1,%2};"
                     :: "l"(gr + 2*qq), "f"(y[2*qq]), "f"(y[2*qq+1])
                     : "memory");
    }
}

// ---------------------------------------------------------------------------
// Kernel 4: graph MLP
// ---------------------------------------------------------------------------
__global__ __launch_bounds__(256) void graph_mlp_kernel(
        const float* __restrict__ W2,
        const float* __restrict__ b2,
        const float* __restrict__ W3,
        const float* __restrict__ b3,
        float* __restrict__ out) {
    __shared__ float sW2[H2 * H2];
    __shared__ float sb2[H2];
    __shared__ float sW3[H2];
    __shared__ float sb3;
    for (int i = threadIdx.x; i < H2 * H2; i += blockDim.x) sW2[i] = W2[i];
    if (threadIdx.x < H2) { sb2[threadIdx.x] = b2[threadIdx.x]; sW3[threadIdx.x] = W3[threadIdx.x]; }
    if (threadIdx.x == 0) sb3 = b3[0];
    __syncthreads();

    int g = blockIdx.x * blockDim.x + threadIdx.x;
    if (g >= N_GRAPHS) return;

    float v[H2];
    const float2* gp = (const float2*)(g_g + (size_t)g * H2);
#pragma unroll
    for (int qq = 0; qq < 5; qq++) {
        float2 tt = gp[qq];
        v[2*qq] = tt.x; v[2*qq+1] = tt.y;
    }

    float o = sb3;
#pragma unroll
    for (int j = 0; j < H2; j++) {
        float h = sb2[j];
#pragma unroll
        for (int k = 0; k < H2; k++) h = fmaf(v[k], sW2[k * H2 + j], h);
        o = fmaf(fmaxf(h, 0.f), sW3[j], o);
    }
    out[g] = o;
}

// ---------------------------------------------------------------------------
extern "C" void kernel_launch(void* const* d_in, const int* in_sizes, int n_in,
                              void* d_out, int out_size) {
    const int*   edge_index = (const int*)  d_in[0];
    const float* node_attr  = (const float*)d_in[1];
    const float* edge_attr  = (const float*)d_in[2];
    const int*   batch      = (const int*)  d_in[3];
    const float* W_msg      = (const float*)d_in[4];
    const float* b_msg      = (const float*)d_in[5];
    const float* b1         = (const float*)d_in[7];
    const float* W1         = (const float*)d_in[6];
    const float* W2         = (const float*)d_in[8];
    const float* b2         = (const float*)d_in[9];
    const float* W3         = (const float*)d_in[10];
    const float* b3         = (const float*)d_in[11];
    float* out = (float*)d_out;

    node_proj_kernel<<<(N_NODES + 255) / 256, 256>>>(node_attr, W_msg);
    edge_kernel<<<(N_EDGES * 4 + 255) / 256, 256>>>(edge_index, edge_attr, W_msg, b_msg);
    node_mlp_kernel<<<(N_NODES + 127) / 128, 128>>>(batch, W1, b1);
    graph_mlp_kernel<<<(N_GRAPHS + 255) / 256, 256>>>(W2, b2, W3, b3, out);
}

// round 5
// speedup vs baseline: 1.2215x; 1.2003x over previous
#include <cuda_runtime.h>
#include <cuda_fp16.h>

#define N_NODES   100000
#define N_EDGES   1600000
#define N_GRAPHS  5000
#define ND        16
#define ED        16
#define HID       20
#define H2        10
#define HP        (HID/2)
#define H2P       (H2/2)
#define PH_STRIDE 32        // half stride per pa/pb row: 32 halves = 64B

// Scratch
__device__ float g_x [N_NODES * HID];                      // 80B rows, dense
__device__ __align__(128) __half g_pa[N_NODES * PH_STRIDE]; // fp16 rows, 64B stride
__device__ __align__(128) __half g_pb[N_NODES * PH_STRIDE];
__device__ float g_g [N_GRAPHS * H2];

// ---- packed f32x2 helpers -------------------------------------------------
__device__ __forceinline__ unsigned long long fma2(unsigned long long a,
                                                   unsigned long long b,
                                                   unsigned long long c) {
    unsigned long long d;
    asm("fma.rn.f32x2 %0, %1, %2, %3;" : "=l"(d) : "l"(a), "l"(b), "l"(c));
    return d;
}
__device__ __forceinline__ unsigned long long bcast2(float x) {
    unsigned long long d;
    asm("mov.b64 %0, {%1, %1};" : "=l"(d) : "f"(x));
    return d;
}
__device__ __forceinline__ float2 unpack2(unsigned long long v) {
    float2 r;
    asm("mov.b64 {%0, %1}, %2;" : "=f"(r.x), "=f"(r.y) : "l"(v));
    return r;
}
__device__ __forceinline__ float2 h2f2(unsigned int h) {
    return __half22float2(*(const __half2*)&h);
}

// ---------------------------------------------------------------------------
// Kernel 1: per-node projections pa = A@Wa, pb = A@Wb  (fp16 out, + zeroing)
// ---------------------------------------------------------------------------
__global__ void node_proj_kernel(const float* __restrict__ node_attr,
                                 const float* __restrict__ W_msg) {
    __shared__ __align__(8) float sWa[ND * HID];
    __shared__ __align__(8) float sWb[ND * HID];
    for (int i = threadIdx.x; i < ND * HID; i += blockDim.x) {
        sWa[i] = W_msg[i];
        sWb[i] = W_msg[ND * HID + i];
    }
    __syncthreads();
    const unsigned long long* wa2 = (const unsigned long long*)sWa;
    const unsigned long long* wb2 = (const unsigned long long*)sWb;

    int n = blockIdx.x * blockDim.x + threadIdx.x;

    if (n < (N_GRAPHS * H2) / 4)
        ((float4*)g_g)[n] = make_float4(0.f, 0.f, 0.f, 0.f);

    if (n >= N_NODES) return;

    // zero this node's g_x row (20 floats, 16B-aligned)
    {
        const float4 z = make_float4(0.f, 0.f, 0.f, 0.f);
        float4* xr = (float4*)(g_x + (size_t)n * HID);
#pragma unroll
        for (int q = 0; q < 5; q++) xr[q] = z;
    }

    float a[ND];
    const float4* ap = (const float4*)(node_attr + (size_t)n * ND);
#pragma unroll
    for (int q = 0; q < 4; q++) {
        float4 v = ap[q];
        a[4*q+0] = v.x; a[4*q+1] = v.y; a[4*q+2] = v.z; a[4*q+3] = v.w;
    }

    unsigned long long acc[HP];
    unsigned int u[HP];

    // pa
#pragma unroll
    for (int p = 0; p < HP; p++) acc[p] = 0ull;
#pragma unroll
    for (int k = 0; k < ND; k++) {
        unsigned long long ak = bcast2(a[k]);
#pragma unroll
        for (int p = 0; p < HP; p++) acc[p] = fma2(ak, wa2[k * HP + p], acc[p]);
    }
#pragma unroll
    for (int p = 0; p < HP; p++) {
        float2 t = unpack2(acc[p]);
        __half2 h = __float22half2_rn(t);
        u[p] = *(unsigned int*)&h;
    }
    {
        char* row = (char*)(g_pa + (size_t)n * PH_STRIDE);
        *(uint4*)(row +  0) = make_uint4(u[0], u[1], u[2], u[3]);
        *(uint4*)(row + 16) = make_uint4(u[4], u[5], u[6], u[7]);
        *(uint2*)(row + 32) = make_uint2(u[8], u[9]);
    }

    // pb
#pragma unroll
    for (int p = 0; p < HP; p++) acc[p] = 0ull;
#pragma unroll
    for (int k = 0; k < ND; k++) {
        unsigned long long ak = bcast2(a[k]);
#pragma unroll
        for (int p = 0; p < HP; p++) acc[p] = fma2(ak, wb2[k * HP + p], acc[p]);
    }
#pragma unroll
    for (int p = 0; p < HP; p++) {
        float2 t = unpack2(acc[p]);
        __half2 h = __float22half2_rn(t);
        u[p] = *(unsigned int*)&h;
    }
    {
        char* row = (char*)(g_pb + (size_t)n * PH_STRIDE);
        *(uint4*)(row +  0) = make_uint4(u[0], u[1], u[2], u[3]);
        *(uint4*)(row + 16) = make_uint4(u[4], u[5], u[6], u[7]);
        *(uint2*)(row + 32) = make_uint2(u[8], u[9]);
    }
}

// ---------------------------------------------------------------------------
// Kernel 2: edge message + scatter-sum
// ---------------------------------------------------------------------------
__global__ __launch_bounds__(256) void edge_kernel(
        const int*   __restrict__ edge_index,
        const float* __restrict__ edge_attr,
        const float* __restrict__ W_msg,
        const float* __restrict__ b_msg) {
    __shared__ __align__(8) float sWe[ED * HID];
    __shared__ __align__(8) float sb[HID];
    for (int i = threadIdx.x; i < ED * HID; i += blockDim.x)
        sWe[i] = W_msg[2 * ND * HID + i];
    for (int i = threadIdx.x; i < HID; i += blockDim.x)
        sb[i] = b_msg[i];
    __syncthreads();
    const unsigned long long* we2 = (const unsigned long long*)sWe;
    const unsigned long long* sb2 = (const unsigned long long*)sb;

    int e = blockIdx.x * blockDim.x + threadIdx.x;
    if (e >= N_EDGES) return;

    int src = __ldg(edge_index + e);
    int dst = __ldg(edge_index + N_EDGES + e);

    // fp16 gathers: 2 sectors per row (40B within a 64B-aligned 64B region)
    const char* par = (const char*)(g_pa + (size_t)src * PH_STRIDE);
    const char* pbr = (const char*)(g_pb + (size_t)dst * PH_STRIDE);
    uint4 A0 = *(const uint4*)(par +  0);
    uint4 A1 = *(const uint4*)(par + 16);
    uint2 A2 = *(const uint2*)(par + 32);
    uint4 B0 = *(const uint4*)(pbr +  0);
    uint4 B1 = *(const uint4*)(pbr + 16);
    uint2 B2 = *(const uint2*)(pbr + 32);

    unsigned long long acc[HP];
#pragma unroll
    for (int p = 0; p < HP; p++) acc[p] = sb2[p];

    const float4* ep = (const float4*)(edge_attr + (size_t)e * ED);
#pragma unroll
    for (int q = 0; q < 4; q++) {
        float4 v = ep[q];
        float ek[4] = {v.x, v.y, v.z, v.w};
#pragma unroll
        for (int t = 0; t < 4; t++) {
            unsigned long long b = bcast2(ek[t]);
#pragma unroll
            for (int p = 0; p < HP; p++)
                acc[p] = fma2(b, we2[(4*q + t) * HP + p], acc[p]);
        }
    }

    unsigned int au[HP] = {A0.x, A0.y, A0.z, A0.w, A1.x, A1.y, A1.z, A1.w, A2.x, A2.y};
    unsigned int bu[HP] = {B0.x, B0.y, B0.z, B0.w, B1.x, B1.y, B1.z, B1.w, B2.x, B2.y};

    float m[HID];
#pragma unroll
    for (int p = 0; p < HP; p++) {
        float2 c = unpack2(acc[p]);
        float2 fa = h2f2(au[p]);
        float2 fb = h2f2(bu[p]);
        m[2*p]   = fmaxf(c.x + fa.x + fb.x, 0.f);
        m[2*p+1] = fmaxf(c.y + fa.y + fb.y, 0.f);
    }

    float* xr = g_x + (size_t)dst * HID;
#pragma unroll
    for (int q = 0; q < 5; q++) {
        asm volatile("red.global.add.v4.f32 [%0], {%1,%2,%3,%4};"
                     :: "l"(xr + 4*q),
                        "f"(m[4*q]), "f"(m[4*q+1]), "f"(m[4*q+2]), "f"(m[4*q+3])
                     : "memory");
    }
}

// ---------------------------------------------------------------------------
// Kernel 3: node MLP + graph pooling
// ---------------------------------------------------------------------------
__global__ __launch_bounds__(128) void node_mlp_kernel(
        const int*   __restrict__ batch,
        const float* __restrict__ W1,
        const float* __restrict__ b1) {
    __shared__ __align__(8) float sW[HID * H2];
    __shared__ __align__(8) float sb[H2];
    for (int i = threadIdx.x; i < HID * H2; i += blockDim.x) sW[i] = W1[i];
    for (int i = threadIdx.x; i < H2; i += blockDim.x) sb[i] = b1[i];
    __syncthreads();
    const unsigned long long* w2 = (const unsigned long long*)sW;
    const unsigned long long* sb2 = (const unsigned long long*)sb;

    int n = blockIdx.x * blockDim.x + threadIdx.x;
    if (n >= N_NODES) return;

    int b = __ldg(batch + n);

    float x[HID];
    const float4* xp = (const float4*)(g_x + (size_t)n * HID);
#pragma unroll
    for (int q = 0; q < 5; q++) {
        float4 v = xp[q];
        x[4*q+0] = v.x; x[4*q+1] = v.y; x[4*q+2] = v.z; x[4*q+3] = v.w;
    }

    unsigned long long acc[H2P];
#pragma unroll
    for (int p = 0; p < H2P; p++) acc[p] = sb2[p];
#pragma unroll
    for (int k = 0; k < HID; k++) {
        unsigned long long xk = bcast2(x[k]);
#pragma unroll
        for (int p = 0; p < H2P; p++) acc[p] = fma2(xk, w2[k * H2P + p], acc[p]);
    }

    float y[H2];
#pragma unroll
    for (int p = 0; p < H2P; p++) {
        float2 t = unpack2(acc[p]);
        y[2*p]   = fmaxf(t.x, 0.f);
        y[2*p+1] = fmaxf(t.y, 0.f);
    }

    float* gr = g_g + (size_t)b * H2;
#pragma unroll
    for (int q = 0; q < 5; q++) {
        asm volatile("red.global.add.v2.f32 [%0], {%1,%2};"
                     :: "l"(gr + 2*q), "f"(y[2*q]), "f"(y[2*q+1])
                     : "memory");
    }
}

// ---------------------------------------------------------------------------
// Kernel 4: graph MLP
// ---------------------------------------------------------------------------
__global__ __launch_bounds__(256) void graph_mlp_kernel(
        const float* __restrict__ W2,
        const float* __restrict__ b2,
        const float* __restrict__ W3,
        const float* __restrict__ b3,
        float* __restrict__ out) {
    __shared__ float sW2[H2 * H2];
    __shared__ float sb2[H2];
    __shared__ float sW3[H2];
    __shared__ float sb3;
    for (int i = threadIdx.x; i < H2 * H2; i += blockDim.x) sW2[i] = W2[i];
    if (threadIdx.x < H2) { sb2[threadIdx.x] = b2[threadIdx.x]; sW3[threadIdx.x] = W3[threadIdx.x]; }
    if (threadIdx.x == 0) sb3 = b3[0];
    __syncthreads();

    int g = blockIdx.x * blockDim.x + threadIdx.x;
    if (g >= N_GRAPHS) return;

    float v[H2];
    const float2* gp = (const float2*)(g_g + (size_t)g * H2);
#pragma unroll
    for (int q = 0; q < 5; q++) {
        float2 t = gp[q];
        v[2*q] = t.x; v[2*q+1] = t.y;
    }

    float o = sb3;
#pragma unroll
    for (int j = 0; j < H2; j++) {
        float h = sb2[j];
#pragma unroll
        for (int k = 0; k < H2; k++) h = fmaf(v[k], sW2[k * H2 + j], h);
        o = fmaf(fmaxf(h, 0.f), sW3[j], o);
    }
    out[g] = o;
}

// ---------------------------------------------------------------------------
extern "C" void kernel_launch(void* const* d_in, const int* in_sizes, int n_in,
                              void* d_out, int out_size) {
    const int*   edge_index = (const int*)  d_in[0];
    const float* node_attr  = (const float*)d_in[1];
    const float* edge_attr  = (const float*)d_in[2];
    const int*   batch      = (const int*)  d_in[3];
    const float* W_msg      = (const float*)d_in[4];
    const float* b_msg      = (const float*)d_in[5];
    const float* W1         = (const float*)d_in[6];
    const float* b1         = (const float*)d_in[7];
    const float* W2         = (const float*)d_in[8];
    const float* b2         = (const float*)d_in[9];
    const float* W3         = (const float*)d_in[10];
    const float* b3         = (const float*)d_in[11];
    float* out = (float*)d_out;

    node_proj_kernel<<<(N_NODES + 255) / 256, 256>>>(node_attr, W_msg);
    edge_kernel<<<(N_EDGES + 255) / 256, 256>>>(edge_index, edge_attr, W_msg, b_msg);
    node_mlp_kernel<<<(N_NODES + 127) / 128, 128>>>(batch, W1, b1);
    graph_mlp_kernel<<<(N_GRAPHS + 255) / 256, 256>>>(W2, b2, W3, b3, out);
}

// round 6
// speedup vs baseline: 1.2868x; 1.0534x over previous
#include <cuda_runtime.h>
#include <cuda_fp16.h>

#define N_NODES   100000
#define N_EDGES   1600000
#define N_GRAPHS  5000
#define ND        16
#define ED        16
#define HID       20
#define H2        10
#define HP        (HID/2)
#define H2P       (H2/2)
#define PH_STRIDE 32        // half stride per pa/pb row: 32 halves = 64B

// Scratch
__device__ float g_x [N_NODES * HID];                       // 80B rows, dense
__device__ __align__(128) __half g_pa[N_NODES * PH_STRIDE]; // fp16 rows, 64B stride
__device__ __align__(128) __half g_pb[N_NODES * PH_STRIDE];
__device__ float g_g [N_GRAPHS * H2];

// ---- packed f32x2 helpers -------------------------------------------------
__device__ __forceinline__ unsigned long long fma2(unsigned long long a,
                                                   unsigned long long b,
                                                   unsigned long long c) {
    unsigned long long d;
    asm("fma.rn.f32x2 %0, %1, %2, %3;" : "=l"(d) : "l"(a), "l"(b), "l"(c));
    return d;
}
__device__ __forceinline__ unsigned long long bcast2(float x) {
    unsigned long long d;
    asm("mov.b64 %0, {%1, %1};" : "=l"(d) : "f"(x));
    return d;
}
__device__ __forceinline__ float2 unpack2(unsigned long long v) {
    float2 r;
    asm("mov.b64 {%0, %1}, %2;" : "=f"(r.x), "=f"(r.y) : "l"(v));
    return r;
}
__device__ __forceinline__ float2 h2f2(unsigned int h) {
    return __half22float2(*(const __half2*)&h);
}

// 256-bit load (Blackwell): 8 consecutive f32 (raw bits) in one LSU op
__device__ __forceinline__ void ldg256(const void* p, float r[8]) {
    asm("ld.global.nc.v8.f32 {%0,%1,%2,%3,%4,%5,%6,%7}, [%8];"
        : "=f"(r[0]), "=f"(r[1]), "=f"(r[2]), "=f"(r[3]),
          "=f"(r[4]), "=f"(r[5]), "=f"(r[6]), "=f"(r[7])
        : "l"(p));
}
__device__ __forceinline__ float2 ldg64(const void* p) {
    float2 r;
    asm("ld.global.nc.v2.f32 {%0,%1}, [%2];" : "=f"(r.x), "=f"(r.y) : "l"(p));
    return r;
}

// ---------------------------------------------------------------------------
// Kernel 1: per-node projections pa = A@Wa, pb = A@Wb  (fp16 out, + zeroing)
// ---------------------------------------------------------------------------
__global__ void node_proj_kernel(const float* __restrict__ node_attr,
                                 const float* __restrict__ W_msg) {
    __shared__ __align__(8) float sWa[ND * HID];
    __shared__ __align__(8) float sWb[ND * HID];
    for (int i = threadIdx.x; i < ND * HID; i += blockDim.x) {
        sWa[i] = W_msg[i];
        sWb[i] = W_msg[ND * HID + i];
    }
    __syncthreads();
    const unsigned long long* wa2 = (const unsigned long long*)sWa;
    const unsigned long long* wb2 = (const unsigned long long*)sWb;

    int n = blockIdx.x * blockDim.x + threadIdx.x;

    if (n < (N_GRAPHS * H2) / 4)
        ((float4*)g_g)[n] = make_float4(0.f, 0.f, 0.f, 0.f);

    if (n >= N_NODES) return;

    // zero this node's g_x row (20 floats)
    {
        const float4 z = make_float4(0.f, 0.f, 0.f, 0.f);
        float4* xr = (float4*)(g_x + (size_t)n * HID);
#pragma unroll
        for (int q = 0; q < 5; q++) xr[q] = z;
    }

    float a[ND];
    const float4* ap = (const float4*)(node_attr + (size_t)n * ND);
#pragma unroll
    for (int q = 0; q < 4; q++) {
        float4 v = ap[q];
        a[4*q+0] = v.x; a[4*q+1] = v.y; a[4*q+2] = v.z; a[4*q+3] = v.w;
    }

    unsigned long long acc[HP];
    unsigned int u[HP];

    // pa
#pragma unroll
    for (int p = 0; p < HP; p++) acc[p] = 0ull;
#pragma unroll
    for (int k = 0; k < ND; k++) {
        unsigned long long ak = bcast2(a[k]);
#pragma unroll
        for (int p = 0; p < HP; p++) acc[p] = fma2(ak, wa2[k * HP + p], acc[p]);
    }
#pragma unroll
    for (int p = 0; p < HP; p++) {
        float2 t = unpack2(acc[p]);
        __half2 h = __float22half2_rn(t);
        u[p] = *(unsigned int*)&h;
    }
    {
        char* row = (char*)(g_pa + (size_t)n * PH_STRIDE);
        *(uint4*)(row +  0) = make_uint4(u[0], u[1], u[2], u[3]);
        *(uint4*)(row + 16) = make_uint4(u[4], u[5], u[6], u[7]);
        *(uint2*)(row + 32) = make_uint2(u[8], u[9]);
    }

    // pb
#pragma unroll
    for (int p = 0; p < HP; p++) acc[p] = 0ull;
#pragma unroll
    for (int k = 0; k < ND; k++) {
        unsigned long long ak = bcast2(a[k]);
#pragma unroll
        for (int p = 0; p < HP; p++) acc[p] = fma2(ak, wb2[k * HP + p], acc[p]);
    }
#pragma unroll
    for (int p = 0; p < HP; p++) {
        float2 t = unpack2(acc[p]);
        __half2 h = __float22half2_rn(t);
        u[p] = *(unsigned int*)&h;
    }
    {
        char* row = (char*)(g_pb + (size_t)n * PH_STRIDE);
        *(uint4*)(row +  0) = make_uint4(u[0], u[1], u[2], u[3]);
        *(uint4*)(row + 16) = make_uint4(u[4], u[5], u[6], u[7]);
        *(uint2*)(row + 32) = make_uint2(u[8], u[9]);
    }
}

// ---------------------------------------------------------------------------
// Kernel 2: edge message + scatter-sum (v8 256-bit loads)
// ---------------------------------------------------------------------------
__global__ __launch_bounds__(256) void edge_kernel(
        const int*   __restrict__ edge_index,
        const float* __restrict__ edge_attr,
        const float* __restrict__ W_msg,
        const float* __restrict__ b_msg) {
    __shared__ __align__(8) float sWe[ED * HID];
    __shared__ __align__(8) float sb[HID];
    for (int i = threadIdx.x; i < ED * HID; i += blockDim.x)
        sWe[i] = W_msg[2 * ND * HID + i];
    for (int i = threadIdx.x; i < HID; i += blockDim.x)
        sb[i] = b_msg[i];
    __syncthreads();
    const unsigned long long* we2 = (const unsigned long long*)sWe;
    const unsigned long long* sb2 = (const unsigned long long*)sb;

    int e = blockIdx.x * blockDim.x + threadIdx.x;
    if (e >= N_EDGES) return;

    int src = __ldg(edge_index + e);
    int dst = __ldg(edge_index + N_EDGES + e);

    // gathers: 2 LSU ops per row (v8 32B + v2 8B)
    const char* par = (const char*)(g_pa + (size_t)src * PH_STRIDE);
    const char* pbr = (const char*)(g_pb + (size_t)dst * PH_STRIDE);
    float A8[8], B8[8];
    ldg256(par, A8);
    float2 A2 = ldg64(par + 32);
    ldg256(pbr, B8);
    float2 B2 = ldg64(pbr + 32);

    // edge_attr: 2× v8
    float ea[ED];
    ldg256(edge_attr + (size_t)e * ED, ea);
    ldg256(edge_attr + (size_t)e * ED + 8, ea + 8);

    unsigned long long acc[HP];
#pragma unroll
    for (int p = 0; p < HP; p++) acc[p] = sb2[p];

#pragma unroll
    for (int k = 0; k < ED; k++) {
        unsigned long long b = bcast2(ea[k]);
#pragma unroll
        for (int p = 0; p < HP; p++)
            acc[p] = fma2(b, we2[k * HP + p], acc[p]);
    }

    unsigned int au[HP] = {
        __float_as_uint(A8[0]), __float_as_uint(A8[1]), __float_as_uint(A8[2]),
        __float_as_uint(A8[3]), __float_as_uint(A8[4]), __float_as_uint(A8[5]),
        __float_as_uint(A8[6]), __float_as_uint(A8[7]),
        __float_as_uint(A2.x),  __float_as_uint(A2.y)};
    unsigned int bu[HP] = {
        __float_as_uint(B8[0]), __float_as_uint(B8[1]), __float_as_uint(B8[2]),
        __float_as_uint(B8[3]), __float_as_uint(B8[4]), __float_as_uint(B8[5]),
        __float_as_uint(B8[6]), __float_as_uint(B8[7]),
        __float_as_uint(B2.x),  __float_as_uint(B2.y)};

    float m[HID];
#pragma unroll
    for (int p = 0; p < HP; p++) {
        float2 c = unpack2(acc[p]);
        float2 fa = h2f2(au[p]);
        float2 fb = h2f2(bu[p]);
        m[2*p]   = fmaxf(c.x + fa.x + fb.x, 0.f);
        m[2*p+1] = fmaxf(c.y + fa.y + fb.y, 0.f);
    }

    float* xr = g_x + (size_t)dst * HID;
#pragma unroll
    for (int q = 0; q < 5; q++) {
        asm volatile("red.global.add.v4.f32 [%0], {%1,%2,%3,%4};"
                     :: "l"(xr + 4*q),
                        "f"(m[4*q]), "f"(m[4*q+1]), "f"(m[4*q+2]), "f"(m[4*q+3])
                     : "memory");
    }
}

// ---------------------------------------------------------------------------
// Kernel 3: node MLP + graph pooling
// ---------------------------------------------------------------------------
__global__ __launch_bounds__(128) void node_mlp_kernel(
        const int*   __restrict__ batch,
        const float* __restrict__ W1,
        const float* __restrict__ b1) {
    __shared__ __align__(8) float sW[HID * H2];
    __shared__ __align__(8) float sb[H2];
    for (int i = threadIdx.x; i < HID * H2; i += blockDim.x) sW[i] = W1[i];
    for (int i = threadIdx.x; i < H2; i += blockDim.x) sb[i] = b1[i];
    __syncthreads();
    const unsigned long long* w2 = (const unsigned long long*)sW;
    const unsigned long long* sb2 = (const unsigned long long*)sb;

    int n = blockIdx.x * blockDim.x + threadIdx.x;
    if (n >= N_NODES) return;

    int b = __ldg(batch + n);

    float x[HID];
    const float4* xp = (const float4*)(g_x + (size_t)n * HID);
#pragma unroll
    for (int q = 0; q < 5; q++) {
        float4 v = xp[q];
        x[4*q+0] = v.x; x[4*q+1] = v.y; x[4*q+2] = v.z; x[4*q+3] = v.w;
    }

    unsigned long long acc[H2P];
#pragma unroll
    for (int p = 0; p < H2P; p++) acc[p] = sb2[p];
#pragma unroll
    for (int k = 0; k < HID; k++) {
        unsigned long long xk = bcast2(x[k]);
#pragma unroll
        for (int p = 0; p < H2P; p++) acc[p] = fma2(xk, w2[k * H2P + p], acc[p]);
    }

    float y[H2];
#pragma unroll
    for (int p = 0; p < H2P; p++) {
        float2 t = unpack2(acc[p]);
        y[2*p]   = fmaxf(t.x, 0.f);
        y[2*p+1] = fmaxf(t.y, 0.f);
    }

    float* gr = g_g + (size_t)b * H2;
#pragma unroll
    for (int q = 0; q < 5; q++) {
        asm volatile("red.global.add.v2.f32 [%0], {%1,%2};"
                     :: "l"(gr + 2*q), "f"(y[2*q]), "f"(y[2*q+1])
                     : "memory");
    }
}

// ---------------------------------------------------------------------------
// Kernel 4: graph MLP
// ---------------------------------------------------------------------------
__global__ __launch_bounds__(256) void graph_mlp_kernel(
        const float* __restrict__ W2,
        const float* __restrict__ b2,
        const float* __restrict__ W3,
        const float* __restrict__ b3,
        float* __restrict__ out) {
    __shared__ float sW2[H2 * H2];
    __shared__ float sb2[H2];
    __shared__ float sW3[H2];
    __shared__ float sb3;
    for (int i = threadIdx.x; i < H2 * H2; i += blockDim.x) sW2[i] = W2[i];
    if (threadIdx.x < H2) { sb2[threadIdx.x] = b2[threadIdx.x]; sW3[threadIdx.x] = W3[threadIdx.x]; }
    if (threadIdx.x == 0) sb3 = b3[0];
    __syncthreads();

    int g = blockIdx.x * blockDim.x + threadIdx.x;
    if (g >= N_GRAPHS) return;

    float v[H2];
    const float2* gp = (const float2*)(g_g + (size_t)g * H2);
#pragma unroll
    for (int q = 0; q < 5; q++) {
        float2 t = gp[q];
        v[2*q] = t.x; v[2*q+1] = t.y;
    }

    float o = sb3;
#pragma unroll
    for (int j = 0; j < H2; j++) {
        float h = sb2[j];
#pragma unroll
        for (int k = 0; k < H2; k++) h = fmaf(v[k], sW2[k * H2 + j], h);
        o = fmaf(fmaxf(h, 0.f), sW3[j], o);
    }
    out[g] = o;
}

// ---------------------------------------------------------------------------
extern "C" void kernel_launch(void* const* d_in, const int* in_sizes, int n_in,
                              void* d_out, int out_size) {
    const int*   edge_index = (const int*)  d_in[0];
    const float* node_attr  = (const float*)d_in[1];
    const float* edge_attr  = (const float*)d_in[2];
    const int*   batch      = (const int*)  d_in[3];
    const float* W_msg      = (const float*)d_in[4];
    const float* b_msg      = (const float*)d_in[5];
    const float* W1         = (const float*)d_in[6];
    const float* b1         = (const float*)d_in[7];
    const float* W2         = (const float*)d_in[8];
    const float* b2         = (const float*)d_in[9];
    const float* W3         = (const float*)d_in[10];
    const float* b3         = (const float*)d_in[11];
    float* out = (float*)d_out;

    node_proj_kernel<<<(N_NODES + 255) / 256, 256>>>(node_attr, W_msg);
    edge_kernel<<<(N_EDGES + 255) / 256, 256>>>(edge_index, edge_attr, W_msg, b_msg);
    node_mlp_kernel<<<(N_NODES + 127) / 128, 128>>>(batch, W1, b1);
    graph_mlp_kernel<<<(N_GRAPHS + 255) / 256, 256>>>(W2, b2, W3, b3, out);
}